// round 1
// baseline (speedup 1.0000x reference)
#include <cuda_runtime.h>

// Conv2d: x (32,128,56,56) f32, w (256,128,3,3) f32, stride 1, pad 1 -> out (32,256,56,56)
// Implicit GEMM: M = 32*56*56 = 100352, N = 256, K = 128*9 = 1152 (tap-major).

#define N_IMG   32
#define C_IN    128
#define HW      56
#define C_OUT   256
#define PIX     (HW * HW)          // 3136
#define M_TOTAL (N_IMG * PIX)      // 100352
#define KTOT    (C_IN * 9)         // 1152
#define NCHUNK  (KTOT / 8)         // 144 chunks of BK=8

// Pre-transposed weights: w_t[(tap*128 + c)*256 + oc]
__device__ float g_wt[KTOT * C_OUT];

__global__ void transpose_w_kernel(const float* __restrict__ w) {
    int i = blockIdx.x * 256 + threadIdx.x;
    if (i >= KTOT * C_OUT) return;
    int oc  = i & 255;
    int kc  = i >> 8;        // tap*128 + c
    int tap = kc >> 7;
    int c   = kc & 127;
    g_wt[i] = w[oc * KTOT + c * 9 + tap];
}

__global__ __launch_bounds__(256, 2)
void conv_implicit_gemm(const float* __restrict__ x, float* __restrict__ out) {
    __shared__ float As[2][8][128];   // [buf][k][m]
    __shared__ float Bs[2][8][128];   // [buf][k][oc]

    const int t   = threadIdx.x;
    const int bm0 = blockIdx.x * 128;       // pixel-tile base
    const int oc0 = blockIdx.y * 128;       // out-channel tile base

    // ---- loader mapping: col = t>>5 (k within chunk), rows = (t&31) + 32*i ----
    const int lcol = t >> 5;   // 0..7
    const int lrow = t & 31;   // 0..31

    int xb_[4];                // n * C_IN * PIX  (base offset into x for image n)
    int oh_[4], ow_[4];
    #pragma unroll
    for (int i = 0; i < 4; i++) {
        int m = bm0 + lrow + 32 * i;       // < 100352, exact multiple tiling
        int n = m / PIX;
        int r = m - n * PIX;
        int oh = r / HW;
        oh_[i] = oh;
        ow_[i] = r - oh * HW;
        xb_[i] = n * (C_IN * PIX);
    }

    // ---- compute mapping (interleaved): m = tx + 16*j, oc = ty + 16*i ----
    const int tx = t & 15;
    const int ty = t >> 4;

    float acc[8][8];
    #pragma unroll
    for (int i = 0; i < 8; i++)
        #pragma unroll
        for (int j = 0; j < 8; j++)
            acc[i][j] = 0.0f;

    // ---- prologue: load chunk 0 into buffer 0 ----
    {
        const int tap = 0;                  // chunk 0 -> tap 0, c0 = 0
        const int dh = -1, dw = -1;         // kh=0, kw=0
        const int c = lcol;
        const int xoff_c = c * PIX;
        #pragma unroll
        for (int i = 0; i < 4; i++) {
            int ih = oh_[i] + dh;
            int iw = ow_[i] + dw;
            bool v = ((unsigned)ih < (unsigned)HW) && ((unsigned)iw < (unsigned)HW);
            As[0][lcol][lrow + 32 * i] =
                v ? __ldg(x + xb_[i] + xoff_c + ih * HW + iw) : 0.0f;
        }
        int koff = (tap * 128 + c) * C_OUT + oc0 + lrow;
        #pragma unroll
        for (int i = 0; i < 4; i++)
            Bs[0][lcol][lrow + 32 * i] = g_wt[koff + 32 * i];
    }
    __syncthreads();

    int buf = 0;
    for (int chunk = 0; chunk < NCHUNK; ++chunk) {
        float a_pf[4], b_pf[4];
        const bool has_next = (chunk + 1 < NCHUNK);

        // ---- prefetch next chunk into registers ----
        if (has_next) {
            int nc   = chunk + 1;
            int tap  = nc >> 4;              // chunk = tap*16 + cc
            int c0   = (nc & 15) << 3;
            int kh   = tap / 3;
            int dw   = (tap - kh * 3) - 1;
            int dh   = kh - 1;
            int c    = c0 + lcol;
            int xoff_c = c * PIX;
            #pragma unroll
            for (int i = 0; i < 4; i++) {
                int ih = oh_[i] + dh;
                int iw = ow_[i] + dw;
                bool v = ((unsigned)ih < (unsigned)HW) && ((unsigned)iw < (unsigned)HW);
                a_pf[i] = v ? __ldg(x + xb_[i] + xoff_c + ih * HW + iw) : 0.0f;
            }
            int koff = (tap * 128 + c) * C_OUT + oc0 + lrow;
            #pragma unroll
            for (int i = 0; i < 4; i++)
                b_pf[i] = g_wt[koff + 32 * i];
        }

        // ---- compute on current buffer ----
        #pragma unroll
        for (int kk = 0; kk < 8; kk++) {
            float ar[8], br[8];
            #pragma unroll
            for (int j = 0; j < 8; j++) ar[j] = As[buf][kk][tx + 16 * j];
            #pragma unroll
            for (int i = 0; i < 8; i++) br[i] = Bs[buf][kk][ty + 16 * i];
            #pragma unroll
            for (int i = 0; i < 8; i++)
                #pragma unroll
                for (int j = 0; j < 8; j++)
                    acc[i][j] = fmaf(br[i], ar[j], acc[i][j]);
        }

        // ---- commit prefetched regs to the other buffer ----
        if (has_next) {
            #pragma unroll
            for (int i = 0; i < 4; i++) {
                As[buf ^ 1][lcol][lrow + 32 * i] = a_pf[i];
                Bs[buf ^ 1][lcol][lrow + 32 * i] = b_pf[i];
            }
        }
        buf ^= 1;
        __syncthreads();
    }

    // ---- epilogue: coalesced stores (consecutive lanes -> consecutive pixels) ----
    #pragma unroll
    for (int j = 0; j < 8; j++) {
        int m = bm0 + tx + 16 * j;
        int n = m / PIX;
        int r = m - n * PIX;
        size_t ob = (size_t)n * (C_OUT * PIX) + r;
        #pragma unroll
        for (int i = 0; i < 8; i++) {
            int oc = oc0 + ty + 16 * i;
            out[ob + (size_t)oc * PIX] = acc[i][j];
        }
    }
}

extern "C" void kernel_launch(void* const* d_in, const int* in_sizes, int n_in,
                              void* d_out, int out_size) {
    const float* x = (const float*)d_in[0];
    const float* w = (const float*)d_in[1];
    float* out = (float*)d_out;

    // 1) transpose weights into tap-major scratch (tiny: 1.18 MB)
    transpose_w_kernel<<<(KTOT * C_OUT + 255) / 256, 256>>>(w);

    // 2) implicit GEMM conv
    dim3 grid(M_TOTAL / 128, C_OUT / 128);   // (784, 2)
    conv_implicit_gemm<<<grid, 256>>>(x, out);
}

// round 3
// speedup vs baseline: 1.8920x; 1.8920x over previous
#include <cuda_runtime.h>
#include <cuda_bf16.h>
#include <stdint.h>

// Conv2d 3x3 s1 p1: x(32,128,56,56) f32, w(256,128,3,3) f32 -> out(32,256,56,56) f32
// Implicit GEMM, mma.sync.m16n8k16.bf16 (sm_80+ path; tcgen05 unavailable: harness
// targets compute_100 without the 'a' feature set).
// 3-pass split precision: D = Ahi*Bhi + Ahi*Blo + Alo*Bhi, fp32 accumulate.

#define N_IMG   32
#define C_IN    128
#define HWD     56
#define PIX     3136
#define C_OUT   256
#define M_TOTAL 100352
#define KTOT    1152
#define BK      32
#define NSTAGE  (KTOT / BK)     // 36

// -------- device scratch (no allocation allowed) --------
__device__ __nv_bfloat16 g_xhi[(size_t)N_IMG * PIX * C_IN];   // NHWC
__device__ __nv_bfloat16 g_xlo[(size_t)N_IMG * PIX * C_IN];   // NHWC
__device__ __nv_bfloat16 g_whi[(size_t)C_OUT * KTOT];         // [oc][k], k = tap*128+c
__device__ __nv_bfloat16 g_wlo[(size_t)C_OUT * KTOT];

// ==================== prep: x NCHW f32 -> NHWC bf16 hi/lo ====================
__global__ void prep_x(const float* __restrict__ x) {
    __shared__ uint16_t shi[128 * 33];
    __shared__ uint16_t slo[128 * 33];
    int n  = blockIdx.x / 98;
    int pt = blockIdx.x - n * 98;
    int p0 = pt * 32;
    int t = threadIdx.x;
    int lane = t & 31;
    #pragma unroll
    for (int i = 0; i < 16; i++) {
        int c = (t >> 5) + 8 * i;
        float v = x[((size_t)n * 128 + c) * PIX + p0 + lane];
        __nv_bfloat16 hi = __float2bfloat16(v);
        __nv_bfloat16 lo = __float2bfloat16(v - __bfloat162float(hi));
        shi[c * 33 + lane] = __bfloat16_as_ushort(hi);
        slo[c * 33 + lane] = __bfloat16_as_ushort(lo);
    }
    __syncthreads();
    int c4 = lane * 4;
    #pragma unroll
    for (int i = 0; i < 4; i++) {
        int pix = (t >> 5) + 8 * i;
        size_t base = ((size_t)n * PIX + p0 + pix) * 128 + c4;
        uint2 vh, vl;
        vh.x = (uint32_t)shi[(c4 + 0) * 33 + pix] | ((uint32_t)shi[(c4 + 1) * 33 + pix] << 16);
        vh.y = (uint32_t)shi[(c4 + 2) * 33 + pix] | ((uint32_t)shi[(c4 + 3) * 33 + pix] << 16);
        vl.x = (uint32_t)slo[(c4 + 0) * 33 + pix] | ((uint32_t)slo[(c4 + 1) * 33 + pix] << 16);
        vl.y = (uint32_t)slo[(c4 + 2) * 33 + pix] | ((uint32_t)slo[(c4 + 3) * 33 + pix] << 16);
        *reinterpret_cast<uint2*>(&g_xhi[base]) = vh;
        *reinterpret_cast<uint2*>(&g_xlo[base]) = vl;
    }
}

// ==================== prep: w OIHW f32 -> [oc][k] bf16 hi/lo, k tap-major ====================
__global__ void prep_w(const float* __restrict__ w) {
    int idx = blockIdx.x * 256 + threadIdx.x;
    if (idx >= C_OUT * KTOT) return;
    int oc = idx / KTOT;
    int k  = idx - oc * KTOT;
    int tap = k >> 7;
    int c   = k & 127;
    float v = w[(size_t)oc * KTOT + c * 9 + tap];
    __nv_bfloat16 hi = __float2bfloat16(v);
    __nv_bfloat16 lo = __float2bfloat16(v - __bfloat162float(hi));
    g_whi[idx] = hi;
    g_wlo[idx] = lo;
}

// ==================== main kernel ====================
// smem per stage buffer (row stride 80B = 32 bf16 + 8 pad, ldmatrix conflict-free):
//   AHI [128][80B] @0, ALO @10240, BHI @20480, BLO @30720 -> 40960B/stage, x2 = 81920B
#define ROWB   80
#define A_HI   0
#define A_LO   10240
#define B_HI   20480
#define B_LO   30720
#define STG_B  40960
#define SMEMSZ (2 * STG_B)

__device__ __forceinline__ uint32_t smem_u32(const void* p) {
    uint32_t a;
    asm("{ .reg .u64 t; cvta.to.shared.u64 t, %1; cvt.u32.u64 %0, t; }" : "=r"(a) : "l"(p));
    return a;
}
#define CP16(dst, src, sz) \
    asm volatile("cp.async.ca.shared.global [%0], [%1], 16, %2;" \
                 :: "r"(dst), "l"(src), "r"(sz) : "memory")
#define CP_COMMIT() asm volatile("cp.async.commit_group;" ::: "memory")
#define CP_WAIT1()  asm volatile("cp.async.wait_group 1;" ::: "memory")
#define CP_WAIT0()  asm volatile("cp.async.wait_group 0;" ::: "memory")

__device__ __forceinline__ void ldsm_x4(uint32_t* r, uint32_t addr) {
    asm volatile("ldmatrix.sync.aligned.m8n8.x4.shared.b16 {%0,%1,%2,%3}, [%4];"
                 : "=r"(r[0]), "=r"(r[1]), "=r"(r[2]), "=r"(r[3]) : "r"(addr));
}
__device__ __forceinline__ void mma16816(float* c, const uint32_t* a, const uint32_t* b) {
    asm volatile(
        "mma.sync.aligned.m16n8k16.row.col.f32.bf16.bf16.f32 "
        "{%0,%1,%2,%3}, {%4,%5,%6,%7}, {%8,%9}, {%0,%1,%2,%3};"
        : "+f"(c[0]), "+f"(c[1]), "+f"(c[2]), "+f"(c[3])
        : "r"(a[0]), "r"(a[1]), "r"(a[2]), "r"(a[3]), "r"(b[0]), "r"(b[1]));
}

__global__ __launch_bounds__(256, 1)
void conv_mma(float* __restrict__ out) {
    extern __shared__ __align__(128) char smem[];
    const uint32_t sb = smem_u32(smem);

    const int t   = threadIdx.x;
    const int lid = t & 31;
    const int wid = t >> 5;
    const int bm0 = blockIdx.x * 128;
    const int oc0 = blockIdx.y * 128;

    // ---- loader mapping: part = hi/lo, r = row (pixel for A, oc for B) ----
    const int part = t >> 7;           // 0: hi, 1: lo
    const int r    = t & 127;
    const int p    = bm0 + r;
    const int n    = p / PIX;
    const int prem = p - n * PIX;
    const int oh   = prem / HWD;
    const int ow   = prem - oh * HWD;
    const char* xsrc_base = part ? (const char*)g_xlo : (const char*)g_xhi;
    const char* wsrc_base = part ? (const char*)g_wlo : (const char*)g_whi;
    const size_t xrow0 = (size_t)n * PIX * 256;                 // bytes: (n*PIX)*128*2
    const char* wsrc_row = wsrc_base + (size_t)(oc0 + r) * KTOT * 2;

    // ---- compute mapping: 2x4 warps, warp tile 64x32 ----
    const int mw = wid >> 2;           // 0..1
    const int nw = wid & 3;            // 0..3
    const int m_base = mw * 64;
    const int n_base = nw * 32;
    const int j   = lid >> 3;          // ldmatrix sub-tile selector
    const int rin = lid & 7;
    const int a_lane = ((j & 1) * 8 + rin) * ROWB + (j >> 1) * 16;
    const int b_lane = ((j >> 1) * 8 + rin) * ROWB + (j & 1) * 16;

    float acc[4][4][4];
    #pragma unroll
    for (int i = 0; i < 4; i++)
        #pragma unroll
        for (int jj = 0; jj < 4; jj++)
            #pragma unroll
            for (int q = 0; q < 4; q++) acc[i][jj][q] = 0.0f;

    // ---- stage issue ----
    auto issue = [&](int s, int buf) {
        const int k0  = s * BK;
        const int tap = k0 >> 7;
        const int c0  = k0 & 127;
        const int dh = tap / 3 - 1, dw = tap % 3 - 1;
        const int ih = oh + dh, iw = ow + dw;
        const bool v = ((unsigned)ih < (unsigned)HWD) && ((unsigned)iw < (unsigned)HWD);
        const uint32_t vsz = v ? 16u : 0u;
        const uint32_t stg = sb + buf * STG_B;
        const char* asrc = xsrc_base + xrow0 + ((size_t)(v ? ih * HWD + iw : 0) * 128 + c0) * 2;
        const uint32_t adst = stg + part * 10240 + A_HI + r * ROWB;
        #pragma unroll
        for (int q = 0; q < 4; q++) CP16(adst + q * 16, asrc + q * 16, vsz);
        const char* bsrc = wsrc_row + k0 * 2;
        const uint32_t bdst = stg + part * 10240 + B_HI + r * ROWB;
        #pragma unroll
        for (int q = 0; q < 4; q++) CP16(bdst + q * 16, bsrc + q * 16, 16u);
        CP_COMMIT();
    };

    issue(0, 0);

    int buf = 0;
    for (int s = 0; s < NSTAGE; ++s) {
        if (s + 1 < NSTAGE) { issue(s + 1, buf ^ 1); CP_WAIT1(); }
        else                { CP_WAIT0(); }
        __syncthreads();

        const uint32_t stg = sb + buf * STG_B;
        const uint32_t abase = stg + (m_base * ROWB) + a_lane;
        const uint32_t bbase = stg + (n_base * ROWB) + b_lane;

        #pragma unroll
        for (int kk = 0; kk < 2; kk++) {
            uint32_t ah[4][4], al[4][4], bh[2][4], bl[2][4];
            #pragma unroll
            for (int mt = 0; mt < 4; mt++) {
                ldsm_x4(ah[mt], abase + A_HI + mt * (16 * ROWB) + kk * 32);
                ldsm_x4(al[mt], abase + A_LO + mt * (16 * ROWB) + kk * 32);
            }
            #pragma unroll
            for (int nt = 0; nt < 2; nt++) {
                ldsm_x4(bh[nt], bbase + B_HI + nt * (16 * ROWB) + kk * 32);
                ldsm_x4(bl[nt], bbase + B_LO + nt * (16 * ROWB) + kk * 32);
            }
            #pragma unroll
            for (int mt = 0; mt < 4; mt++)
                #pragma unroll
                for (int n8 = 0; n8 < 4; n8++) {
                    const uint32_t* bph = &bh[n8 >> 1][(n8 & 1) * 2];
                    const uint32_t* bpl = &bl[n8 >> 1][(n8 & 1) * 2];
                    mma16816(acc[mt][n8], ah[mt], bph);
                    mma16816(acc[mt][n8], ah[mt], bpl);
                    mma16816(acc[mt][n8], al[mt], bph);
                }
        }
        __syncthreads();
        buf ^= 1;
    }

    // ---- epilogue: NCHW stores ----
    const int erow = lid >> 2;         // 0..7
    const int ecol = (lid & 3) * 2;    // 0,2,4,6
    #pragma unroll
    for (int mt = 0; mt < 4; mt++) {
        #pragma unroll
        for (int half = 0; half < 2; half++) {
            const int pix = bm0 + m_base + mt * 16 + erow + half * 8;
            const int nn  = pix / PIX;
            const int pr  = pix - nn * PIX;
            float* ob = out + (size_t)nn * C_OUT * PIX + pr;
            #pragma unroll
            for (int n8 = 0; n8 < 4; n8++) {
                const int oc = oc0 + n_base + n8 * 8 + ecol;
                ob[(size_t)oc * PIX]       = acc[mt][n8][half * 2];
                ob[(size_t)(oc + 1) * PIX] = acc[mt][n8][half * 2 + 1];
            }
        }
    }
}

// ==================== launch ====================
extern "C" void kernel_launch(void* const* d_in, const int* in_sizes, int n_in,
                              void* d_out, int out_size) {
    const float* x = (const float*)d_in[0];
    const float* w = (const float*)d_in[1];
    float* out = (float*)d_out;

    static int smem_set = 0;
    if (!smem_set) {
        cudaFuncSetAttribute(conv_mma, cudaFuncAttributeMaxDynamicSharedMemorySize, SMEMSZ);
        smem_set = 1;
    }

    prep_x<<<N_IMG * 98, 256>>>(x);
    prep_w<<<(C_OUT * KTOT + 255) / 256, 256>>>(w);
    dim3 grid(M_TOTAL / 128, C_OUT / 128);   // (784, 2)
    conv_mma<<<grid, 256, SMEMSZ>>>(out);
}

// round 6
// speedup vs baseline: 5.0560x; 2.6724x over previous
#include <cuda_runtime.h>
#include <cuda_fp16.h>
#include <stdint.h>

// Conv2d 3x3 s1 p1: x(32,128,56,56) f32, w(256,128,3,3) f32 -> out(32,256,56,56) f32
// Implicit GEMM, single-pass fp16 mma.sync.m16n8k16 (fp32 accumulate).
// M=100352, N=256, K=1152 tap-major. rel_err ~2-4e-4 expected (global norm).

#define N_IMG   32
#define C_IN    128
#define HWD     56
#define PIX     3136
#define C_OUT   256
#define M_TOTAL 100352
#define KTOT    1152
#define BK      32
#define NSTAGE  (KTOT / BK)     // 36
#define RING    4

// -------- device scratch (no allocation allowed) --------
__device__ __half g_x[(size_t)N_IMG * PIX * C_IN];           // NHWC fp16
__device__ __half g_wst[(size_t)NSTAGE * C_OUT * BK];        // stage-major: [s][oc][32]

// ==================== prep: x NCHW f32 -> NHWC fp16 ====================
__global__ void prep_x(const float* __restrict__ x) {
    __shared__ uint16_t sh[128 * 33];
    int n  = blockIdx.x / 98;
    int pt = blockIdx.x - n * 98;
    int p0 = pt * 32;
    int t = threadIdx.x;
    int lane = t & 31;
    #pragma unroll
    for (int i = 0; i < 16; i++) {
        int c = (t >> 5) + 8 * i;
        float v = x[((size_t)n * 128 + c) * PIX + p0 + lane];
        sh[c * 33 + lane] = __half_as_ushort(__float2half_rn(v));
    }
    __syncthreads();
    int c4 = lane * 4;
    #pragma unroll
    for (int i = 0; i < 4; i++) {
        int pix = (t >> 5) + 8 * i;
        size_t base = ((size_t)n * PIX + p0 + pix) * 128 + c4;
        uint2 vh;
        vh.x = (uint32_t)sh[(c4 + 0) * 33 + pix] | ((uint32_t)sh[(c4 + 1) * 33 + pix] << 16);
        vh.y = (uint32_t)sh[(c4 + 2) * 33 + pix] | ((uint32_t)sh[(c4 + 3) * 33 + pix] << 16);
        *reinterpret_cast<uint2*>(&g_x[base]) = vh;
    }
}

// ==================== prep: w OIHW f32 -> stage-major fp16 [s][oc][32] ====================
__global__ void prep_w(const float* __restrict__ w) {
    int idx = blockIdx.x * 256 + threadIdx.x;
    if (idx >= NSTAGE * C_OUT * BK) return;
    int i  = idx & 31;                 // k within stage
    int oc = (idx >> 5) & 255;
    int s  = idx >> 13;
    int k  = s * BK + i;               // tap-major k
    int tap = k >> 7;
    int c   = k & 127;
    g_wst[idx] = __float2half_rn(w[(size_t)oc * KTOT + c * 9 + tap]);
}

// ==================== main kernel ====================
// stage: A[128 rows][80B] @0 (10240B), B[128 rows][80B] @10240 -> 20480B/stage, RING=4 -> 81920B
#define ROWB   80
#define A_OFF  0
#define B_OFF  10240
#define STG_B  20480
#define SMEMSZ (RING * STG_B)

__device__ __forceinline__ uint32_t smem_u32(const void* p) {
    uint32_t a;
    asm("{ .reg .u64 t; cvta.to.shared.u64 t, %1; cvt.u32.u64 %0, t; }" : "=r"(a) : "l"(p));
    return a;
}
#define CP16(dst, src, sz) \
    asm volatile("cp.async.ca.shared.global [%0], [%1], 16, %2;" \
                 :: "r"(dst), "l"(src), "r"(sz) : "memory")
#define CP_COMMIT()  asm volatile("cp.async.commit_group;" ::: "memory")
#define CP_WAITG(n)  asm volatile("cp.async.wait_group %0;" :: "n"(n) : "memory")

__device__ __forceinline__ void ldsm_x4(uint32_t* r, uint32_t addr) {
    asm volatile("ldmatrix.sync.aligned.m8n8.x4.shared.b16 {%0,%1,%2,%3}, [%4];"
                 : "=r"(r[0]), "=r"(r[1]), "=r"(r[2]), "=r"(r[3]) : "r"(addr));
}
__device__ __forceinline__ void mma16816(float* c, const uint32_t* a, const uint32_t* b) {
    asm volatile(
        "mma.sync.aligned.m16n8k16.row.col.f32.f16.f16.f32 "
        "{%0,%1,%2,%3}, {%4,%5,%6,%7}, {%8,%9}, {%0,%1,%2,%3};"
        : "+f"(c[0]), "+f"(c[1]), "+f"(c[2]), "+f"(c[3])
        : "r"(a[0]), "r"(a[1]), "r"(a[2]), "r"(a[3]), "r"(b[0]), "r"(b[1]));
}

__global__ __launch_bounds__(256, 2)
void conv_mma(float* __restrict__ out) {
    extern __shared__ __align__(128) char smem[];
    const uint32_t sb = smem_u32(smem);

    const int t   = threadIdx.x;
    const int lid = t & 31;
    const int wid = t >> 5;
    const int bm0 = blockIdx.x * 128;
    const int oc0 = blockIdx.y * 128;

    // ---- loader mapping: t<128 -> A row t; t>=128 -> B row t-128 ----
    const int isA = (t < 128);
    const int r   = t & 127;
    const int p    = bm0 + r;
    const int n    = p / PIX;
    const int prem = p - n * PIX;
    const int oh   = prem / HWD;
    const int ow   = prem - oh * HWD;
    const char* xbase = (const char*)g_x + (size_t)n * PIX * 256;    // bytes
    const char* wbase = (const char*)g_wst;

    // ---- compute mapping: 2x4 warps, warp tile 64x32 ----
    const int mw = wid >> 2;
    const int nw = wid & 3;
    const int m_base = mw * 64;
    const int n_base = nw * 32;
    const int j   = lid >> 3;
    const int rin = lid & 7;
    const int a_lane = ((j & 1) * 8 + rin) * ROWB + (j >> 1) * 16;
    const int b_lane = ((j >> 1) * 8 + rin) * ROWB + (j & 1) * 16;

    float acc[4][4][4];
    #pragma unroll
    for (int i = 0; i < 4; i++)
        #pragma unroll
        for (int jj = 0; jj < 4; jj++)
            #pragma unroll
            for (int q = 0; q < 4; q++) acc[i][jj][q] = 0.0f;

    auto issue = [&](int s) {
        const uint32_t stg = sb + (s & 3) * STG_B;
        if (isA) {
            const int k0  = (s & 3) * 32;          // c0 within channel dim
            const int tap = s >> 2;
            const int dh = tap / 3 - 1, dw = tap % 3 - 1;
            const int ih = oh + dh, iw = ow + dw;
            const bool v = ((unsigned)ih < (unsigned)HWD) && ((unsigned)iw < (unsigned)HWD);
            const uint32_t vsz = v ? 16u : 0u;
            const char* src = xbase + ((size_t)(v ? ih * HWD + iw : 0) * 128 + k0) * 2;
            const uint32_t dst = stg + A_OFF + r * ROWB;
            #pragma unroll
            for (int q = 0; q < 4; q++) CP16(dst + q * 16, src + q * 16, vsz);
        } else {
            // B rows start at this CTA's out-channel block (oc0) — the R4 bug fix.
            const char* src = wbase + (size_t)s * 16384 + (size_t)(oc0 + r) * 64;
            const uint32_t dst = stg + B_OFF + r * ROWB;
            #pragma unroll
            for (int q = 0; q < 4; q++) CP16(dst + q * 16, src + q * 16, 16u);
        }
        CP_COMMIT();
    };

    issue(0); issue(1); issue(2);

    for (int s = 0; s < NSTAGE; ++s) {
        // wait until group s complete: allowed pending = min(2, 35-s)
        const int rem = NSTAGE - 1 - s;
        if (rem >= 2)      CP_WAITG(2);
        else if (rem == 1) CP_WAITG(1);
        else               CP_WAITG(0);
        __syncthreads();            // data visible; all prior reads of reused buf done
        if (s + 3 < NSTAGE) issue(s + 3);

        const uint32_t stg = sb + (s & 3) * STG_B;
        const uint32_t abase = stg + A_OFF + m_base * ROWB + a_lane;
        const uint32_t bbase = stg + B_OFF + n_base * ROWB + b_lane;

        #pragma unroll
        for (int kk = 0; kk < 2; kk++) {
            uint32_t ah[4][4], bh[2][4];
            #pragma unroll
            for (int mt = 0; mt < 4; mt++)
                ldsm_x4(ah[mt], abase + mt * (16 * ROWB) + kk * 32);
            #pragma unroll
            for (int nt = 0; nt < 2; nt++)
                ldsm_x4(bh[nt], bbase + nt * (16 * ROWB) + kk * 32);
            #pragma unroll
            for (int mt = 0; mt < 4; mt++)
                #pragma unroll
                for (int n8 = 0; n8 < 4; n8++)
                    mma16816(acc[mt][n8], ah[mt], &bh[n8 >> 1][(n8 & 1) * 2]);
        }
        // note: next iteration's __syncthreads orders these reads before buffer reuse
    }

    // ---- epilogue: NCHW stores ----
    const int erow = lid >> 2;
    const int ecol = (lid & 3) * 2;
    #pragma unroll
    for (int mt = 0; mt < 4; mt++) {
        #pragma unroll
        for (int half = 0; half < 2; half++) {
            const int pix = bm0 + m_base + mt * 16 + erow + half * 8;
            const int nn  = pix / PIX;
            const int pr  = pix - nn * PIX;
            float* ob = out + (size_t)nn * C_OUT * PIX + pr;
            #pragma unroll
            for (int n8 = 0; n8 < 4; n8++) {
                const int oc = oc0 + n_base + n8 * 8 + ecol;
                ob[(size_t)oc * PIX]       = acc[mt][n8][half * 2];
                ob[(size_t)(oc + 1) * PIX] = acc[mt][n8][half * 2 + 1];
            }
        }
    }
}

// ==================== launch ====================
extern "C" void kernel_launch(void* const* d_in, const int* in_sizes, int n_in,
                              void* d_out, int out_size) {
    const float* x = (const float*)d_in[0];
    const float* w = (const float*)d_in[1];
    float* out = (float*)d_out;

    static int smem_set = 0;
    if (!smem_set) {
        cudaFuncSetAttribute(conv_mma, cudaFuncAttributeMaxDynamicSharedMemorySize, SMEMSZ);
        smem_set = 1;
    }

    prep_x<<<N_IMG * 98, 256>>>(x);
    prep_w<<<(NSTAGE * C_OUT * BK + 255) / 256, 256>>>(w);
    dim3 grid(M_TOTAL / 128, C_OUT / 128);   // (784, 2)
    conv_mma<<<grid, 256, SMEMSZ>>>(out);
}